// round 1
// baseline (speedup 1.0000x reference)
#include <cuda_runtime.h>
#include <math_constants.h>

#define NN 4096
#define FF 32
#define UU 32
#define NHH 2
#define CAP 2048

// Scratch (device globals — no allocation allowed)
__device__ float g_Xr[NHH * NN * UU];   // [h][n][u]
__device__ float g_Xi[NHH * NN * UU];
__device__ float g_sr[NHH * NN];
__device__ float g_si[NHH * NN];
__device__ float g_nr[NHH * NN];
__device__ float g_ni[NHH * NN];

// ---------------------------------------------------------------------------
// Kernel 1: X = H @ W (per head, real/imag) + attention dot products
// One warp per node. 256 threads/block -> 8 nodes/block -> 512 blocks.
// ---------------------------------------------------------------------------
__global__ void __launch_bounds__(256) proj_kernel(
    const float* __restrict__ Hr, const float* __restrict__ Hi,
    const float* __restrict__ W,  const float* __restrict__ a1,
    const float* __restrict__ a2)
{
    __shared__ float sW[NHH][FF][UU];   // 8KB
    __shared__ float sa1[NHH][UU];
    __shared__ float sa2[NHH][UU];

    int tid = threadIdx.x;
    for (int i = tid; i < NHH * FF * UU; i += 256) ((float*)sW)[i] = W[i];
    if (tid < NHH * UU) {
        ((float*)sa1)[tid] = a1[tid];
        ((float*)sa2)[tid] = a2[tid];
    }
    __syncthreads();

    int warp = tid >> 5, lane = tid & 31;
    int n = blockIdx.x * 8 + warp;
    if (n >= NN) return;

    float hr = Hr[n * FF + lane];
    float hi = Hi[n * FF + lane];

    #pragma unroll
    for (int h = 0; h < NHH; h++) {
        float xr = 0.f, xi = 0.f;
        #pragma unroll
        for (int f = 0; f < FF; f++) {
            float w  = sW[h][f][lane];
            xr += __shfl_sync(0xffffffffu, hr, f) * w;
            xi += __shfl_sync(0xffffffffu, hi, f) * w;
        }
        g_Xr[(h * NN + n) * UU + lane] = xr;
        g_Xi[(h * NN + n) * UU + lane] = xi;

        float pr1 = xr * sa1[h][lane];
        float pr2 = xr * sa2[h][lane];
        float pi1 = xi * sa1[h][lane];
        float pi2 = xi * sa2[h][lane];
        #pragma unroll
        for (int o = 16; o > 0; o >>= 1) {
            pr1 += __shfl_xor_sync(0xffffffffu, pr1, o);
            pr2 += __shfl_xor_sync(0xffffffffu, pr2, o);
            pi1 += __shfl_xor_sync(0xffffffffu, pi1, o);
            pi2 += __shfl_xor_sync(0xffffffffu, pi2, o);
        }
        if (lane == 0) {
            g_sr[h * NN + n] = pr1;
            g_nr[h * NN + n] = pr2;
            g_si[h * NN + n] = pi1;
            g_ni[h * NN + n] = pi2;
        }
    }
}

// ---------------------------------------------------------------------------
// Kernel 2: sparse masked softmax + complex weighted aggregation.
// One block per row i. Scan A[i,:] (float4, coalesced), build nonzero list,
// softmax over support (exact vs dense: exp(-1e10 - m) == 0.0f in fp32),
// gather X rows and accumulate.
// ---------------------------------------------------------------------------
__global__ void __launch_bounds__(256) attn_kernel(
    const float* __restrict__ A, float* __restrict__ out)
{
    __shared__ int   s_idx[CAP];            // 8 KB
    __shared__ float s_ev[NHH][2][CAP];     // 32 KB: logits -> exp weights in-place
    __shared__ float s_inv[NHH][2];
    __shared__ float s_acc[NHH][4][UU];
    __shared__ int   s_cnt;

    int i   = blockIdx.x;
    int tid = threadIdx.x;
    if (tid == 0) s_cnt = 0;
    __syncthreads();

    // Phase A: scan row, collect nonzero column indices
    const float4* Arow = (const float4*)(A + (size_t)i * NN);
    for (int t = tid; t < NN / 4; t += 256) {
        float4 v = Arow[t];
        if (v.x != 0.f) { int p = atomicAdd(&s_cnt, 1); if (p < CAP) s_idx[p] = 4 * t + 0; }
        if (v.y != 0.f) { int p = atomicAdd(&s_cnt, 1); if (p < CAP) s_idx[p] = 4 * t + 1; }
        if (v.z != 0.f) { int p = atomicAdd(&s_cnt, 1); if (p < CAP) s_idx[p] = 4 * t + 2; }
        if (v.w != 0.f) { int p = atomicAdd(&s_cnt, 1); if (p < CAP) s_idx[p] = 4 * t + 3; }
    }
    __syncthreads();
    int cnt = min(s_cnt, CAP);

    // Phase B: logits with leaky_relu(0.2)
    for (int t = tid; t < cnt; t += 256) {
        int j = s_idx[t];
        #pragma unroll
        for (int h = 0; h < NHH; h++) {
            float e1 = g_sr[h * NN + i] + g_nr[h * NN + j];
            e1 = (e1 >= 0.f) ? e1 : 0.2f * e1;
            float e2 = g_si[h * NN + i] + g_ni[h * NN + j];
            e2 = (e2 >= 0.f) ? e2 : 0.2f * e2;
            s_ev[h][0][t] = e1;
            s_ev[h][1][t] = e2;
        }
    }
    __syncthreads();

    // Phase C: per-(head, component) softmax normalization (warps 0..3)
    int warp = tid >> 5, lane = tid & 31;
    if (warp < 4) {
        int h = warp >> 1, c = warp & 1;
        float m = -CUDART_INF_F;
        for (int t = lane; t < cnt; t += 32) m = fmaxf(m, s_ev[h][c][t]);
        #pragma unroll
        for (int o = 16; o > 0; o >>= 1) m = fmaxf(m, __shfl_xor_sync(0xffffffffu, m, o));
        float s = 0.f;
        for (int t = lane; t < cnt; t += 32) {
            float w = __expf(s_ev[h][c][t] - m);
            s_ev[h][c][t] = w;     // overwrite logit with unnormalized weight
            s += w;
        }
        #pragma unroll
        for (int o = 16; o > 0; o >>= 1) s += __shfl_xor_sync(0xffffffffu, s, o);
        if (lane == 0) s_inv[h][c] = 1.f / s;
    }
    __syncthreads();

    // Phase D: weighted gather-accumulate.
    // 256 threads = 32 u-lanes x (2 heads x 4 quantities)
    // q: 0 -> w1*Xr, 1 -> w2*Xi, 2 -> w1*Xi, 3 -> w2*Xr
    {
        int u   = tid & 31;
        int idx = tid >> 5;       // 0..7
        int h   = idx >> 2;       // 0..1
        int q   = idx & 3;        // 0..3
        const float* X = (q == 0 || q == 3) ? g_Xr : g_Xi;
        int c = (q == 0 || q == 2) ? 0 : 1;
        float acc = 0.f;
        for (int t = 0; t < cnt; t++) {
            int j = s_idx[t];                        // broadcast
            acc += s_ev[h][c][t] * X[(h * NN + j) * UU + u];  // coalesced 128B line
        }
        s_acc[h][q][u] = acc;
    }
    __syncthreads();

    // Combine complex parts and store
    if (tid < 128) {
        int u    = tid & 31;
        int part = (tid >> 5) & 1;   // 0 = real, 1 = imag
        int h    = (tid >> 6) & 1;
        float inv1 = s_inv[h][0], inv2 = s_inv[h][1];
        float val;
        size_t base;
        if (part == 0) {
            val  = inv1 * s_acc[h][0][u] - inv2 * s_acc[h][1][u];
            base = 0;
        } else {
            val  = inv1 * s_acc[h][2][u] + inv2 * s_acc[h][3][u];
            base = (size_t)NN * NHH * UU;
        }
        out[base + (size_t)i * (NHH * UU) + h * UU + u] = val;
    }
}

extern "C" void kernel_launch(void* const* d_in, const int* in_sizes, int n_in,
                              void* d_out, int out_size)
{
    const float* Hr = (const float*)d_in[0];
    const float* Hi = (const float*)d_in[1];
    const float* A  = (const float*)d_in[2];
    const float* W  = (const float*)d_in[3];
    const float* a1 = (const float*)d_in[4];
    const float* a2 = (const float*)d_in[5];
    float* out = (float*)d_out;

    proj_kernel<<<512, 256>>>(Hr, Hi, W, a1, a2);
    attn_kernel<<<NN, 256>>>(A, out);
}

// round 2
// speedup vs baseline: 1.1323x; 1.1323x over previous
#include <cuda_runtime.h>
#include <math_constants.h>

#define NN 4096
#define FF 32
#define UU 32
#define NHH 2
#define CAP 128   // nnz/row ~ Binomial(4096,0.005): mean 20.5, sigma 4.5 -> 128 is >20 sigma

// Scratch (device globals — no allocation allowed)
__device__ float g_Xr[NHH * NN * UU];   // [h][n][u]
__device__ float g_Xi[NHH * NN * UU];
__device__ float g_sr[NHH * NN];
__device__ float g_si[NHH * NN];
__device__ float g_nr[NHH * NN];
__device__ float g_ni[NHH * NN];

// ---------------------------------------------------------------------------
// Kernel 1: X = H @ W (per head, real/imag) + attention dot products
// One warp per node. 256 threads/block -> 8 nodes/block -> 512 blocks.
// ---------------------------------------------------------------------------
__global__ void __launch_bounds__(256) proj_kernel(
    const float* __restrict__ Hr, const float* __restrict__ Hi,
    const float* __restrict__ W,  const float* __restrict__ a1,
    const float* __restrict__ a2)
{
    __shared__ float sW[NHH][FF][UU];   // 8KB
    __shared__ float sa1[NHH][UU];
    __shared__ float sa2[NHH][UU];

    int tid = threadIdx.x;
    for (int i = tid; i < NHH * FF * UU; i += 256) ((float*)sW)[i] = W[i];
    if (tid < NHH * UU) {
        ((float*)sa1)[tid] = a1[tid];
        ((float*)sa2)[tid] = a2[tid];
    }
    __syncthreads();

    int warp = tid >> 5, lane = tid & 31;
    int n = blockIdx.x * 8 + warp;
    if (n >= NN) return;

    float hr = Hr[n * FF + lane];
    float hi = Hi[n * FF + lane];

    #pragma unroll
    for (int h = 0; h < NHH; h++) {
        float xr = 0.f, xi = 0.f;
        #pragma unroll
        for (int f = 0; f < FF; f++) {
            float w  = sW[h][f][lane];
            xr += __shfl_sync(0xffffffffu, hr, f) * w;
            xi += __shfl_sync(0xffffffffu, hi, f) * w;
        }
        g_Xr[(h * NN + n) * UU + lane] = xr;
        g_Xi[(h * NN + n) * UU + lane] = xi;

        float pr1 = xr * sa1[h][lane];
        float pr2 = xr * sa2[h][lane];
        float pi1 = xi * sa1[h][lane];
        float pi2 = xi * sa2[h][lane];
        #pragma unroll
        for (int o = 16; o > 0; o >>= 1) {
            pr1 += __shfl_xor_sync(0xffffffffu, pr1, o);
            pr2 += __shfl_xor_sync(0xffffffffu, pr2, o);
            pi1 += __shfl_xor_sync(0xffffffffu, pi1, o);
            pi2 += __shfl_xor_sync(0xffffffffu, pi2, o);
        }
        if (lane == 0) {
            g_sr[h * NN + n] = pr1;
            g_nr[h * NN + n] = pr2;
            g_si[h * NN + n] = pi1;
            g_ni[h * NN + n] = pi2;
        }
    }
}

// ---------------------------------------------------------------------------
// Kernel 2: sparse masked softmax + complex weighted aggregation.
// One block per row i. Front-batched float4 streaming scan of A[i,:]
// (MLP=4/thread, __ldcs streaming hint), shared nonzero list, per-(head,comp)
// warp softmax (exact vs dense: exp(logit - 1e10 - m) == 0.0f in fp32),
// coalesced weighted gathers of L2-resident X rows.
// ---------------------------------------------------------------------------
__global__ void __launch_bounds__(256, 8) attn_kernel(
    const float* __restrict__ A, float* __restrict__ out)
{
    __shared__ int   s_idx[CAP];            // 512 B
    __shared__ float s_ev[NHH][2][CAP];     // 2 KB
    __shared__ float s_inv[NHH][2];
    __shared__ float s_acc[NHH][4][UU];     // 1 KB
    __shared__ int   s_cnt;

    int i   = blockIdx.x;
    int tid = threadIdx.x;
    if (tid == 0) s_cnt = 0;
    __syncthreads();

    // Phase A: scan row. 4096 floats = 1024 float4 = 4 per thread, all
    // issued up front so the warp has 4 outstanding DRAM loads.
    const float4* Arow = (const float4*)(A + (size_t)i * NN);
    float4 v0 = __ldcs(Arow + tid);
    float4 v1 = __ldcs(Arow + tid + 256);
    float4 v2 = __ldcs(Arow + tid + 512);
    float4 v3 = __ldcs(Arow + tid + 768);

    #pragma unroll
    for (int k = 0; k < 4; k++) {
        float4 v = (k == 0) ? v0 : (k == 1) ? v1 : (k == 2) ? v2 : v3;
        int base = 4 * (tid + 256 * k);
        if (v.x != 0.f) { int p = atomicAdd(&s_cnt, 1); if (p < CAP) s_idx[p] = base + 0; }
        if (v.y != 0.f) { int p = atomicAdd(&s_cnt, 1); if (p < CAP) s_idx[p] = base + 1; }
        if (v.z != 0.f) { int p = atomicAdd(&s_cnt, 1); if (p < CAP) s_idx[p] = base + 2; }
        if (v.w != 0.f) { int p = atomicAdd(&s_cnt, 1); if (p < CAP) s_idx[p] = base + 3; }
    }
    __syncthreads();
    int cnt = min(s_cnt, CAP);

    // Phase B: logits with leaky_relu(0.2)
    for (int t = tid; t < cnt; t += 256) {
        int j = s_idx[t];
        #pragma unroll
        for (int h = 0; h < NHH; h++) {
            float e1 = g_sr[h * NN + i] + g_nr[h * NN + j];
            e1 = (e1 >= 0.f) ? e1 : 0.2f * e1;
            float e2 = g_si[h * NN + i] + g_ni[h * NN + j];
            e2 = (e2 >= 0.f) ? e2 : 0.2f * e2;
            s_ev[h][0][t] = e1;
            s_ev[h][1][t] = e2;
        }
    }
    __syncthreads();

    // Phase C: per-(head, component) softmax normalization (warps 0..3)
    int warp = tid >> 5, lane = tid & 31;
    if (warp < 4) {
        int h = warp >> 1, c = warp & 1;
        float m = -CUDART_INF_F;
        for (int t = lane; t < cnt; t += 32) m = fmaxf(m, s_ev[h][c][t]);
        #pragma unroll
        for (int o = 16; o > 0; o >>= 1) m = fmaxf(m, __shfl_xor_sync(0xffffffffu, m, o));
        float s = 0.f;
        for (int t = lane; t < cnt; t += 32) {
            float w = __expf(s_ev[h][c][t] - m);
            s_ev[h][c][t] = w;     // overwrite logit with unnormalized weight
            s += w;
        }
        #pragma unroll
        for (int o = 16; o > 0; o >>= 1) s += __shfl_xor_sync(0xffffffffu, s, o);
        if (lane == 0) s_inv[h][c] = 1.f / s;
    }
    __syncthreads();

    // Phase D: weighted gather-accumulate.
    // 256 threads = 32 u-lanes x (2 heads x 4 quantities)
    // q: 0 -> w1*Xr, 1 -> w2*Xi, 2 -> w1*Xi, 3 -> w2*Xr
    {
        int u   = tid & 31;
        int idx = tid >> 5;       // 0..7
        int h   = idx >> 2;       // 0..1
        int q   = idx & 3;        // 0..3
        const float* X = (q == 0 || q == 3) ? g_Xr : g_Xi;
        int c = (q == 0 || q == 2) ? 0 : 1;
        float acc = 0.f;
        #pragma unroll 4
        for (int t = 0; t < cnt; t++) {
            int j = s_idx[t];                                 // LDS broadcast
            acc += s_ev[h][c][t] * X[(h * NN + j) * UU + u];  // coalesced 128B line (L2-hot)
        }
        s_acc[h][q][u] = acc;
    }
    __syncthreads();

    // Combine complex parts and store
    if (tid < 128) {
        int u    = tid & 31;
        int part = (tid >> 5) & 1;   // 0 = real, 1 = imag
        int h    = (tid >> 6) & 1;
        float inv1 = s_inv[h][0], inv2 = s_inv[h][1];
        float val;
        size_t base;
        if (part == 0) {
            val  = inv1 * s_acc[h][0][u] - inv2 * s_acc[h][1][u];
            base = 0;
        } else {
            val  = inv1 * s_acc[h][2][u] + inv2 * s_acc[h][3][u];
            base = (size_t)NN * NHH * UU;
        }
        out[base + (size_t)i * (NHH * UU) + h * UU + u] = val;
    }
}

extern "C" void kernel_launch(void* const* d_in, const int* in_sizes, int n_in,
                              void* d_out, int out_size)
{
    const float* Hr = (const float*)d_in[0];
    const float* Hi = (const float*)d_in[1];
    const float* A  = (const float*)d_in[2];
    const float* W  = (const float*)d_in[3];
    const float* a1 = (const float*)d_in[4];
    const float* a2 = (const float*)d_in[5];
    float* out = (float*)d_out;

    proj_kernel<<<512, 256>>>(Hr, Hi, W, a1, a2);
    attn_kernel<<<NN, 256>>>(A, out);
}

// round 3
// speedup vs baseline: 1.3019x; 1.1498x over previous
#include <cuda_runtime.h>
#include <math_constants.h>

#define NN 4096
#define FF 32
#define UU 32
#define NHH 2
#define CAPC 64   // nnz/row ~ Binomial(4096,0.005): mean 20.5, sigma 4.5; 64 is ~9.7 sigma

// Scratch (device globals — no allocation allowed)
__device__ float g_Xr[NHH * NN * UU];   // [h][n][u]
__device__ float g_Xi[NHH * NN * UU];
__device__ float g_sr[NHH * NN];
__device__ float g_si[NHH * NN];
__device__ float g_nr[NHH * NN];
__device__ float g_ni[NHH * NN];
__device__ int   g_cnt[NN];
__device__ int   g_cols[NN * CAPC];

// ---------------------------------------------------------------------------
// Kernel 1 (fused): blocks [0,512) = projection; blocks [512, 512+NN) = A scan.
// Scan blocks stream one A row each and exit immediately — no consumer phases,
// so SMs stay saturated with outstanding DRAM loads.
// ---------------------------------------------------------------------------
__global__ void __launch_bounds__(256) proj_scan_kernel(
    const float* __restrict__ Hr, const float* __restrict__ Hi,
    const float* __restrict__ W,  const float* __restrict__ a1,
    const float* __restrict__ a2, const float* __restrict__ A)
{
    __shared__ float sW[NHH][FF][UU];   // 8KB (proj only)
    __shared__ float sa1[NHH][UU];
    __shared__ float sa2[NHH][UU];
    __shared__ int   s_idx[CAPC];
    __shared__ int   s_cnt;

    int tid = threadIdx.x;

    if (blockIdx.x >= 512) {
        // ---- A-row scan: one row per block ----
        int row = blockIdx.x - 512;
        if (tid == 0) s_cnt = 0;
        __syncthreads();

        const float4* Arow = (const float4*)(A + (size_t)row * NN);
        float4 v0 = __ldcs(Arow + tid);
        float4 v1 = __ldcs(Arow + tid + 256);
        float4 v2 = __ldcs(Arow + tid + 512);
        float4 v3 = __ldcs(Arow + tid + 768);

        #pragma unroll
        for (int k = 0; k < 4; k++) {
            float4 v = (k == 0) ? v0 : (k == 1) ? v1 : (k == 2) ? v2 : v3;
            int base = 4 * (tid + 256 * k);
            if (v.x != 0.f) { int p = atomicAdd(&s_cnt, 1); if (p < CAPC) s_idx[p] = base + 0; }
            if (v.y != 0.f) { int p = atomicAdd(&s_cnt, 1); if (p < CAPC) s_idx[p] = base + 1; }
            if (v.z != 0.f) { int p = atomicAdd(&s_cnt, 1); if (p < CAPC) s_idx[p] = base + 2; }
            if (v.w != 0.f) { int p = atomicAdd(&s_cnt, 1); if (p < CAPC) s_idx[p] = base + 3; }
        }
        __syncthreads();
        int cnt = min(s_cnt, CAPC);
        if (tid < cnt) g_cols[row * CAPC + tid] = s_idx[tid];
        if (tid == 0)  g_cnt[row] = cnt;
        return;
    }

    // ---- Projection: one warp per node, 8 nodes per block ----
    for (int i = tid; i < NHH * FF * UU; i += 256) ((float*)sW)[i] = W[i];
    if (tid < NHH * UU) {
        ((float*)sa1)[tid] = a1[tid];
        ((float*)sa2)[tid] = a2[tid];
    }
    __syncthreads();

    int warp = tid >> 5, lane = tid & 31;
    int n = blockIdx.x * 8 + warp;

    float hr = Hr[n * FF + lane];
    float hi = Hi[n * FF + lane];

    #pragma unroll
    for (int h = 0; h < NHH; h++) {
        float xr = 0.f, xi = 0.f;
        #pragma unroll
        for (int f = 0; f < FF; f++) {
            float w  = sW[h][f][lane];
            xr += __shfl_sync(0xffffffffu, hr, f) * w;
            xi += __shfl_sync(0xffffffffu, hi, f) * w;
        }
        g_Xr[(h * NN + n) * UU + lane] = xr;
        g_Xi[(h * NN + n) * UU + lane] = xi;

        float pr1 = xr * sa1[h][lane];
        float pr2 = xr * sa2[h][lane];
        float pi1 = xi * sa1[h][lane];
        float pi2 = xi * sa2[h][lane];
        #pragma unroll
        for (int o = 16; o > 0; o >>= 1) {
            pr1 += __shfl_xor_sync(0xffffffffu, pr1, o);
            pr2 += __shfl_xor_sync(0xffffffffu, pr2, o);
            pi1 += __shfl_xor_sync(0xffffffffu, pi1, o);
            pi2 += __shfl_xor_sync(0xffffffffu, pi2, o);
        }
        if (lane == 0) {
            g_sr[h * NN + n] = pr1;
            g_nr[h * NN + n] = pr2;
            g_si[h * NN + n] = pi1;
            g_ni[h * NN + n] = pi2;
        }
    }
}

// ---------------------------------------------------------------------------
// Kernel 2: warp-per-row softmax + complex weighted aggregation.
// All inputs (CSR lists, X tables) are tiny and L2-hot.
// Sparse softmax == dense masked softmax exactly: exp(logit - 1e10 - m)
// underflows to 0.0f in fp32 since every row contains its self-loop.
// ---------------------------------------------------------------------------
__global__ void __launch_bounds__(256) gather_kernel(float* __restrict__ out)
{
    __shared__ float s_w[8][4][CAPC];   // per-warp: 4 logit/weight series, 8KB

    int warp = threadIdx.x >> 5, lane = threadIdx.x & 31;
    int i = blockIdx.x * 8 + warp;

    int cnt = min(g_cnt[i], CAPC);
    const int* __restrict__ cols = g_cols + i * CAPC;

    float sr0 = g_sr[i],      si0 = g_si[i];
    float sr1 = g_sr[NN + i], si1 = g_si[NN + i];

    // logits with leaky_relu(0.2). Series: 0=(h0,E1) 1=(h0,E2) 2=(h1,E1) 3=(h1,E2)
    for (int t = lane; t < cnt; t += 32) {
        int j = cols[t];
        float e;
        e = sr0 + g_nr[j];      s_w[warp][0][t] = (e >= 0.f) ? e : 0.2f * e;
        e = si0 + g_ni[j];      s_w[warp][1][t] = (e >= 0.f) ? e : 0.2f * e;
        e = sr1 + g_nr[NN + j]; s_w[warp][2][t] = (e >= 0.f) ? e : 0.2f * e;
        e = si1 + g_ni[NN + j]; s_w[warp][3][t] = (e >= 0.f) ? e : 0.2f * e;
    }
    __syncwarp();

    // per-series softmax normalization
    float inv[4];
    #pragma unroll
    for (int c = 0; c < 4; c++) {
        float m = -CUDART_INF_F;
        for (int t = lane; t < cnt; t += 32) m = fmaxf(m, s_w[warp][c][t]);
        #pragma unroll
        for (int o = 16; o > 0; o >>= 1) m = fmaxf(m, __shfl_xor_sync(0xffffffffu, m, o));
        float s = 0.f;
        for (int t = lane; t < cnt; t += 32) {
            float w = __expf(s_w[warp][c][t] - m);
            s_w[warp][c][t] = w;
            s += w;
        }
        #pragma unroll
        for (int o = 16; o > 0; o >>= 1) s += __shfl_xor_sync(0xffffffffu, s, o);
        inv[c] = 1.f / s;
    }
    __syncwarp();

    // aggregation: lane = u. 8 accumulators, 4 coalesced 128B loads per t.
    float a1r0 = 0.f, a1i0 = 0.f, a2r0 = 0.f, a2i0 = 0.f;
    float a1r1 = 0.f, a1i1 = 0.f, a2r1 = 0.f, a2i1 = 0.f;
    #pragma unroll 2
    for (int t = 0; t < cnt; t++) {
        int j = cols[t];
        float w10 = s_w[warp][0][t];
        float w20 = s_w[warp][1][t];
        float w11 = s_w[warp][2][t];
        float w21 = s_w[warp][3][t];
        float xr0 = g_Xr[j * UU + lane];
        float xi0 = g_Xi[j * UU + lane];
        float xr1 = g_Xr[(NN + j) * UU + lane];
        float xi1 = g_Xi[(NN + j) * UU + lane];
        a1r0 += w10 * xr0;  a1i0 += w10 * xi0;
        a2r0 += w20 * xr0;  a2i0 += w20 * xi0;
        a1r1 += w11 * xr1;  a1i1 += w11 * xi1;
        a2r1 += w21 * xr1;  a2i1 += w21 * xi1;
    }

    // out layout: [real plane NN x 64][imag plane NN x 64], feature = h*32+u
    size_t ro = (size_t)i * (NHH * UU);
    size_t io = (size_t)NN * NHH * UU + ro;
    out[ro + lane]            = inv[0] * a1r0 - inv[1] * a2i0;
    out[ro + UU + lane]       = inv[2] * a1r1 - inv[3] * a2i1;
    out[io + lane]            = inv[0] * a1i0 + inv[1] * a2r0;
    out[io + UU + lane]       = inv[2] * a1i1 + inv[3] * a2r1;
}

extern "C" void kernel_launch(void* const* d_in, const int* in_sizes, int n_in,
                              void* d_out, int out_size)
{
    const float* Hr = (const float*)d_in[0];
    const float* Hi = (const float*)d_in[1];
    const float* A  = (const float*)d_in[2];
    const float* W  = (const float*)d_in[3];
    const float* a1 = (const float*)d_in[4];
    const float* a2 = (const float*)d_in[5];
    float* out = (float*)d_out;

    proj_scan_kernel<<<512 + NN, 256>>>(Hr, Hi, W, a1, a2, A);
    gather_kernel<<<NN / 8, 256>>>(out);
}